// round 12
// baseline (speedup 1.0000x reference)
#include <cuda_runtime.h>
#include <cuda_bf16.h>
#include <cstdint>
#include <math.h>

#define D_FEAT 128
#define MAXN   100000
#define MAXE   6400000

typedef __nv_bfloat16 bf16;

// ---------------- static device scratch (no allocations allowed) -------------
__device__ float g_hu[(size_t)MAXN * 128];
__device__ float g_hv[(size_t)MAXN * 128];
__device__ bf16  g_tot_hi[(size_t)MAXN * 384];
__device__ bf16  g_tot_lo[(size_t)MAXN * 384];
__device__ bf16  g_t2_hi[(size_t)MAXN * 384];
__device__ bf16  g_t2_lo[(size_t)MAXN * 384];
__device__ bf16  g_w1t_hi[128 * 128], g_w1t_lo[128 * 128];
__device__ bf16  g_w2t_hi[128 * 128], g_w2t_lo[128 * 128];
__device__ bf16  g_wgt_hi[384 * 384], g_wgt_lo[384 * 384];
__device__ bf16  g_wat_hi[128 * 384], g_wat_lo[128 * 384];
__device__ unsigned      g_esrc[MAXE];
__device__ int           g_cnt[MAXN];
__device__ int           g_row[MAXN + 1];
__device__ int           g_cur[MAXN + 1];
__device__ int           g_part[1024];
__device__ int           g_base[1024];
__device__ unsigned char g_flag[MAXN];

// ----------------------------- helpers ----------------------------------------
__device__ __forceinline__ uint32_t smem_u32(const void* p) {
    uint32_t a;
    asm("{ .reg .u64 t; cvta.to.shared.u64 t, %1; cvt.u32.u64 %0, t; }"
        : "=r"(a) : "l"(p));
    return a;
}
__device__ __forceinline__ void split1(float v, bf16& h, bf16& l) {
    h = __float2bfloat16_rn(v);
    l = __float2bfloat16_rn(v - __bfloat162float(h));
}
__device__ __forceinline__ uint32_t pck(bf16 a, bf16 b) {
    return ((uint32_t)__bfloat16_as_ushort(b) << 16) | __bfloat16_as_ushort(a);
}
__device__ __forceinline__ void split4_store(bf16* hi, bf16* lo, size_t off, float4 v) {
    bf16 h0, h1, h2, h3, l0, l1, l2, l3;
    split1(v.x, h0, l0); split1(v.y, h1, l1);
    split1(v.z, h2, l2); split1(v.w, h3, l3);
    uint2 uh = make_uint2(pck(h0, h1), pck(h2, h3));
    uint2 ul = make_uint2(pck(l0, l1), pck(l2, l3));
    *(uint2*)(hi + off) = uh;
    *(uint2*)(lo + off) = ul;
}
__device__ __forceinline__ float bfl(uint32_t u) {
    return __bfloat162float(__ushort_as_bfloat16((unsigned short)(u & 0xffff)));
}
__device__ __forceinline__ float bfh(uint32_t u) {
    return __bfloat162float(__ushort_as_bfloat16((unsigned short)(u >> 16)));
}
__device__ __forceinline__ void ldmx4(uint32_t* r, uint32_t addr) {
    asm volatile("ldmatrix.sync.aligned.m8n8.x4.shared.b16 {%0,%1,%2,%3}, [%4];"
                 : "=r"(r[0]), "=r"(r[1]), "=r"(r[2]), "=r"(r[3]) : "r"(addr));
}
__device__ __forceinline__ void mma16816(float* c, const uint32_t* a,
                                         uint32_t b0, uint32_t b1) {
    asm volatile(
        "mma.sync.aligned.m16n8k16.row.col.f32.bf16.bf16.f32 "
        "{%0,%1,%2,%3}, {%4,%5,%6,%7}, {%8,%9}, {%0,%1,%2,%3};"
        : "+f"(c[0]), "+f"(c[1]), "+f"(c[2]), "+f"(c[3])
        : "r"(a[0]), "r"(a[1]), "r"(a[2]), "r"(a[3]), "r"(b0), "r"(b1));
}
// swizzled byte offset within a [128 rows x 128B] tile (K-chunk 64)
__device__ __forceinline__ uint32_t swz(int row, int g16) {
    return ((uint32_t)row << 7) + (((uint32_t)g16 ^ ((uint32_t)row & 7)) << 4);
}
// swizzled byte offset within a [128 rows x 64B] tile (K-chunk 32)
__device__ __forceinline__ uint32_t swz32(int row, int g16) {
    return ((uint32_t)row << 6) + (((uint32_t)g16 ^ (((uint32_t)row >> 1) & 3)) << 4);
}
#define CP16(dst, src) \
    asm volatile("cp.async.cg.shared.global [%0], [%1], 16;" :: "r"(dst), "l"(src))
#define CP_COMMIT() asm volatile("cp.async.commit_group;")

// ------------------------------- small kernels -------------------------------
// two transposed weight splits in one launch (r1 then r2)
__global__ void k_wsplit2(const float* __restrict__ W1, bf16* __restrict__ b1h,
                          bf16* __restrict__ b1l,
                          const float* __restrict__ W2, bf16* __restrict__ b2h,
                          bf16* __restrict__ b2l) {
    int i = blockIdx.x * blockDim.x + threadIdx.x;
    const int KN = 128 * 128;
    const float* W = (i < KN) ? W1 : W2;
    bf16* bh = (i < KN) ? b1h : b2h;
    bf16* bl = (i < KN) ? b1l : b2l;
    int j = (i < KN) ? i : i - KN;
    if (j >= KN) return;
    int n = j >> 7, k = j & 127;
    bf16 h, l; split1(W[(size_t)k * 128 + n], h, l);
    bh[j] = h; bl[j] = l;
}

__global__ void k_wsplit(const float* __restrict__ W, bf16* __restrict__ bhi,
                         bf16* __restrict__ blo, int K, int N) {
    int i = blockIdx.x * blockDim.x + threadIdx.x;
    if (i >= K * N) return;
    int n = i / K, k = i % K;
    bf16 h, l; split1(W[(size_t)k * N + n], h, l);
    bhi[i] = h; blo[i] = l;
}

__global__ void k_hist(const int* __restrict__ e1, const int* __restrict__ e2,
                       int E1, int E2) {
    int stride = gridDim.x * blockDim.x;
    int ET = E1 + E2;
    for (int i = blockIdx.x * blockDim.x + threadIdx.x; i < ET; i += stride) {
        int d = (i < E1) ? e1[E1 + i] : e2[E2 + (i - E1)];
        atomicAdd(&g_cnt[d], 1);
    }
}

__global__ void k_scan_a(int n) {
    int b = blockIdx.x, t = threadIdx.x;
    int i0 = b * 512 + t;
    int s = 0;
    if (i0 < n)       s += g_cnt[i0];
    if (i0 + 256 < n) s += g_cnt[i0 + 256];
    __shared__ int sm[256];
    sm[t] = s; __syncthreads();
    for (int off = 128; off > 0; off >>= 1) {
        if (t < off) sm[t] += sm[t + off];
        __syncthreads();
    }
    if (t == 0) g_part[b] = sm[0];
}

__global__ void k_scan_b(int nb, int n) {
    int t = threadIdx.x;
    __shared__ int sm[256];
    sm[t] = (t < nb) ? g_part[t] : 0;
    __syncthreads();
    for (int off = 1; off < 256; off <<= 1) {
        int x = (t >= off) ? sm[t - off] : 0;
        __syncthreads();
        sm[t] += x;
        __syncthreads();
    }
    int excl = (t == 0) ? 0 : sm[t - 1];
    if (t < nb) g_base[t] = excl;
    if (t == 255) { g_row[n] = sm[255]; g_cur[n] = sm[255]; }
}

__global__ void k_scan_c(int n) {
    int b = blockIdx.x, t = threadIdx.x;
    int i0 = b * 512 + t * 2;
    int a0 = (i0 < n)     ? g_cnt[i0]     : 0;
    int a1 = (i0 + 1 < n) ? g_cnt[i0 + 1] : 0;
    __shared__ int sm[256];
    sm[t] = a0 + a1; __syncthreads();
    for (int off = 1; off < 256; off <<= 1) {
        int x = (t >= off) ? sm[t - off] : 0;
        __syncthreads();
        sm[t] += x;
        __syncthreads();
    }
    int excl = (t == 0) ? 0 : sm[t - 1];
    int base = g_base[b] + excl;
    if (i0 < n)     { g_row[i0]     = base;      g_cur[i0]     = base; }
    if (i0 + 1 < n) { g_row[i0 + 1] = base + a0; g_cur[i0 + 1] = base + a0; }
}

__global__ void k_fill(const int* __restrict__ e1, const int* __restrict__ e2,
                       int E1, int E2) {
    int stride = gridDim.x * blockDim.x;
    int ET = E1 + E2;
    for (int i = blockIdx.x * blockDim.x + threadIdx.x; i < ET; i += stride) {
        int s, d; unsigned rel;
        if (i < E1) { s = e1[i]; d = e1[E1 + i]; rel = 0u; }
        else { int j = i - E1; s = e2[j]; d = e2[E2 + j]; rel = 0x80000000u; }
        int pos = atomicAdd(&g_cur[d], 1);
        g_esrc[pos] = (unsigned)s | rel;
    }
}

// ---------------- per-node aggregation: one warp per destination -------------
__device__ __forceinline__ void acc4(float4& s, float4& m, const float4 v) {
    s.x += v.x; s.y += v.y; s.z += v.z; s.w += v.w;
    m.x = fmaxf(m.x, v.x); m.y = fmaxf(m.y, v.y);
    m.z = fmaxf(m.z, v.z); m.w = fmaxf(m.w, v.w);
}
__device__ __forceinline__ const float4* hsel(unsigned p) {
    return (p & 0x80000000u) ? (const float4*)g_hv : (const float4*)g_hu;
}

__global__ void k_aggr(int n0, int n1) {
    int w = n0 + ((blockIdx.x * blockDim.x + threadIdx.x) >> 5);
    int lane = threadIdx.x & 31;
    if (w >= n1) return;
    int beg = g_row[w], end = g_row[w + 1];
    float4 s = make_float4(0.f, 0.f, 0.f, 0.f);
    float4 m = s;  // max clamped to 0 (reference does max(segmax, 0))
    int e = beg;
    for (; e + 3 < end; e += 4) {
        unsigned p0 = g_esrc[e],     p1 = g_esrc[e + 1];
        unsigned p2 = g_esrc[e + 2], p3 = g_esrc[e + 3];
        float4 v0 = __ldg(hsel(p0) + (size_t)(p0 & 0x7fffffffu) * 32 + lane);
        float4 v1 = __ldg(hsel(p1) + (size_t)(p1 & 0x7fffffffu) * 32 + lane);
        float4 v2 = __ldg(hsel(p2) + (size_t)(p2 & 0x7fffffffu) * 32 + lane);
        float4 v3 = __ldg(hsel(p3) + (size_t)(p3 & 0x7fffffffu) * 32 + lane);
        acc4(s, m, v0); acc4(s, m, v1); acc4(s, m, v2); acc4(s, m, v3);
    }
    for (; e < end; e++) {
        unsigned p = g_esrc[e];
        float4 v = __ldg(hsel(p) + (size_t)(p & 0x7fffffffu) * 32 + lane);
        acc4(s, m, v);
    }
    int c = end - beg;
    float inv = (c > 0) ? 1.f / (float)c : 0.f;
    float4 mean = make_float4(s.x * inv, s.y * inv, s.z * inv, s.w * inv);

    float asum = fabsf(s.x) + fabsf(s.y) + fabsf(s.z) + fabsf(s.w)
               + fabsf(mean.x) + fabsf(mean.y) + fabsf(mean.z) + fabsf(mean.w)
               + fabsf(m.x) + fabsf(m.y) + fabsf(m.z) + fabsf(m.w);
    #pragma unroll
    for (int off = 16; off > 0; off >>= 1)
        asum += __shfl_xor_sync(0xffffffffu, asum, off);

    size_t rb = (size_t)w * 384 + lane * 4;
    split4_store(g_tot_hi, g_tot_lo, rb,       s);
    split4_store(g_tot_hi, g_tot_lo, rb + 128, mean);
    split4_store(g_tot_hi, g_tot_lo, rb + 256, m);
    if (lane == 0) g_flag[w] = (asum == 0.f) ? 1 : 0;
}

// ------ transforms: bf16-split GEMM, fp32 A split in-kernel (proven R8/R9) ---
template <int K, int NGLOB>
__global__ __launch_bounds__(256, 2)
void k_mma(const float* __restrict__ A,
           const bf16* __restrict__ Bhi, const bf16* __restrict__ Blo,
           float* __restrict__ C, int M)
{
    extern __shared__ char sm_[];
    const uint32_t sbase = smem_u32(sm_);
    const int tid = threadIdx.x;
    const int bm = blockIdx.y * 128;
    const int bn = blockIdx.x * 128;
    const int wid = tid >> 5, lane = tid & 31;
    const int wmo = (wid >> 2) * 64;
    const int wno = (wid & 3) * 32;

    float c[4][4][4];
    #pragma unroll
    for (int i = 0; i < 4; i++)
        #pragma unroll
        for (int j = 0; j < 4; j++)
            #pragma unroll
            for (int r = 0; r < 4; r++) c[i][j][r] = 0.f;

    for (int kc = 0; kc < K / 64; kc++) {
        #pragma unroll
        for (int it = 0; it < 4; it++) {
            int tsk = tid + it * 256;
            int r = tsk >> 3, g = tsk & 7;
            int gr = bm + r;
            float4 f0 = make_float4(0.f, 0.f, 0.f, 0.f), f1 = f0;
            if (gr < M) {
                const float4* p = (const float4*)(A + (size_t)gr * K + kc * 64 + g * 8);
                f0 = p[0]; f1 = p[1];
            }
            bf16 h[8], l[8];
            split1(f0.x, h[0], l[0]); split1(f0.y, h[1], l[1]);
            split1(f0.z, h[2], l[2]); split1(f0.w, h[3], l[3]);
            split1(f1.x, h[4], l[4]); split1(f1.y, h[5], l[5]);
            split1(f1.z, h[6], l[6]); split1(f1.w, h[7], l[7]);
            uint4 uh = make_uint4(pck(h[0], h[1]), pck(h[2], h[3]),
                                  pck(h[4], h[5]), pck(h[6], h[7]));
            uint4 ul = make_uint4(pck(l[0], l[1]), pck(l[2], l[3]),
                                  pck(l[4], l[5]), pck(l[6], l[7]));
            uint32_t off = swz(r, g);
            *(uint4*)(sm_ + off)         = uh;
            *(uint4*)(sm_ + 16384 + off) = ul;
        }
        #pragma unroll
        for (int it = 0; it < 4; it++) {
            int tsk = tid + it * 256;
            int r = tsk >> 3, g = tsk & 7;
            uint32_t off = swz(r, g);
            *(uint4*)(sm_ + 32768 + off) =
                *(const uint4*)(Bhi + (size_t)(bn + r) * K + kc * 64 + g * 8);
            *(uint4*)(sm_ + 49152 + off) =
                *(const uint4*)(Blo + (size_t)(bn + r) * K + kc * 64 + g * 8);
        }
        __syncthreads();

        #pragma unroll
        for (int ks = 0; ks < 4; ks++) {
            uint32_t ah[4][4], al[4][4], bh[2][4], bl[2][4];
            #pragma unroll
            for (int mf = 0; mf < 4; mf++) {
                int row = wmo + mf * 16 + (lane & 15);
                int g = ks * 2 + (lane >> 4);
                uint32_t o = swz(row, g);
                ldmx4(ah[mf], sbase + o);
                ldmx4(al[mf], sbase + 16384 + o);
            }
            #pragma unroll
            for (int np = 0; np < 2; np++) {
                int row = wno + np * 16 + ((lane >> 4) << 3) + (lane & 7);
                int g = ks * 2 + ((lane >> 3) & 1);
                uint32_t o = swz(row, g);
                ldmx4(bh[np], sbase + 32768 + o);
                ldmx4(bl[np], sbase + 49152 + o);
            }
            #pragma unroll
            for (int mf = 0; mf < 4; mf++)
                #pragma unroll
                for (int nf = 0; nf < 4; nf++)
                    mma16816(c[mf][nf], ah[mf],
                             bh[nf >> 1][(nf & 1) * 2], bh[nf >> 1][(nf & 1) * 2 + 1]);
            #pragma unroll
            for (int mf = 0; mf < 4; mf++)
                #pragma unroll
                for (int nf = 0; nf < 4; nf++)
                    mma16816(c[mf][nf], al[mf],
                             bh[nf >> 1][(nf & 1) * 2], bh[nf >> 1][(nf & 1) * 2 + 1]);
            #pragma unroll
            for (int mf = 0; mf < 4; mf++)
                #pragma unroll
                for (int nf = 0; nf < 4; nf++)
                    mma16816(c[mf][nf], ah[mf],
                             bl[nf >> 1][(nf & 1) * 2], bl[nf >> 1][(nf & 1) * 2 + 1]);
        }
        __syncthreads();
    }

    #pragma unroll
    for (int mf = 0; mf < 4; mf++) {
        int r0 = bm + wmo + mf * 16 + (lane >> 2);
        #pragma unroll
        for (int nf = 0; nf < 4; nf++) {
            int col = bn + wno + nf * 8 + (lane & 3) * 2;
            #pragma unroll
            for (int h = 0; h < 2; h++) {
                int row = r0 + h * 8;
                if (row >= M) continue;
                *(float2*)(C + (size_t)row * NGLOB + col) =
                    make_float2(c[mf][nf][h * 2], c[mf][nf][h * 2 + 1]);
            }
        }
    }
}

// ------ gate/aggr GEMMs: all-bf16 operands, cp.async 2-stage double buffer ---
// C = A[M,K] @ B[NGLOB,K]^T, 3-term: Ah*Bh + Al*Bh + Ah*Bl
// (2-term measured FAIL at 1.4e-3 in R7 — do not retry.)
// row0 = global row offset of this chunk (for g_flag indexing).
// EPI 1: t = Thi+Tlo; r = t * sigmoid(result + bias); write split(r) -> Chi/Clo
// EPI 2: Cf = result + bias, zeroed where g_flag[row0+row]
template <int K, int NGLOB, int EPI>
__global__ __launch_bounds__(256, 2)
void k_mma2(const bf16* __restrict__ Ahi, const bf16* __restrict__ Alo,
            const bf16* __restrict__ Bhi, const bf16* __restrict__ Blo,
            const float* __restrict__ bias,
            const bf16* __restrict__ Thi, const bf16* __restrict__ Tlo,
            bf16* __restrict__ Chi, bf16* __restrict__ Clo,
            float* __restrict__ Cf, int M, int row0)
{
    constexpr int NKC = K / 32;
    extern __shared__ char sm_[];
    // per stage (32 KB): Ah[0,8K) Al[8K,16K) Bh[16K,24K) Bl[24K,32K)
    const uint32_t sbase = smem_u32(sm_);
    const int tid = threadIdx.x;
    const int bm = blockIdx.y * 128;
    const int bn = blockIdx.x * 128;
    const int wid = tid >> 5, lane = tid & 31;
    const int wmo = (wid >> 2) * 64;
    const int wno = (wid & 3) * 32;

    float c[4][4][4];
    #pragma unroll
    for (int i = 0; i < 4; i++)
        #pragma unroll
        for (int j = 0; j < 4; j++)
            #pragma unroll
            for (int r = 0; r < 4; r++) c[i][j][r] = 0.f;

    int r0s = tid >> 2, g0s = tid & 3;
    int r1s = (tid + 256) >> 2, g1s = tid & 3;
    int ga0 = bm + r0s; if (ga0 >= M) ga0 = M - 1;
    int ga1 = bm + r1s; if (ga1 >= M) ga1 = M - 1;
    uint32_t o0 = swz32(r0s, g0s), o1 = swz32(r1s, g1s);

    auto stage = [&](int kc, int buf) {
        uint32_t sb = sbase + buf * 32768;
        const bf16* pa;
        pa = Ahi + (size_t)ga0 * K + kc * 32 + g0s * 8; CP16(sb + o0, pa);
        pa = Ahi + (size_t)ga1 * K + kc * 32 + g1s * 8; CP16(sb + o1, pa);
        pa = Alo + (size_t)ga0 * K + kc * 32 + g0s * 8; CP16(sb + 8192 + o0, pa);
        pa = Alo + (size_t)ga1 * K + kc * 32 + g1s * 8; CP16(sb + 8192 + o1, pa);
        pa = Bhi + (size_t)(bn + r0s) * K + kc * 32 + g0s * 8; CP16(sb + 16384 + o0, pa);
        pa = Bhi + (size_t)(bn + r1s) * K + kc * 32 + g1s * 8; CP16(sb + 16384 + o1, pa);
        pa = Blo + (size_t)(bn + r0s) * K + kc * 32 + g0s * 8; CP16(sb + 24576 + o0, pa);
        pa = Blo + (size_t)(bn + r1s) * K + kc * 32 + g1s * 8; CP16(sb + 24576 + o1, pa);
        CP_COMMIT();
    };

    stage(0, 0);
    for (int kc = 0; kc < NKC; kc++) {
        if (kc + 1 < NKC) {
            stage(kc + 1, (kc + 1) & 1);
            asm volatile("cp.async.wait_group 1;");
        } else {
            asm volatile("cp.async.wait_group 0;");
        }
        __syncthreads();
        const uint32_t sb = sbase + (kc & 1) * 32768;

        #pragma unroll
        for (int ks = 0; ks < 2; ks++) {
            uint32_t ah[4][4], al[4][4], bh[2][4], bl[2][4];
            #pragma unroll
            for (int mf = 0; mf < 4; mf++) {
                int row = wmo + mf * 16 + (lane & 15);
                int g = ks * 2 + (lane >> 4);
                uint32_t o = swz32(row, g);
                ldmx4(ah[mf], sb + o);
                ldmx4(al[mf], sb + 8192 + o);
            }
            #pragma unroll
            for (int np = 0; np < 2; np++) {
                int row = wno + np * 16 + ((lane >> 4) << 3) + (lane & 7);
                int g = ks * 2 + ((lane >> 3) & 1);
                uint32_t o = swz32(row, g);
                ldmx4(bh[np], sb + 16384 + o);
                ldmx4(bl[np], sb + 24576 + o);
            }
            #pragma unroll
            for (int mf = 0; mf < 4; mf++)
                #pragma unroll
                for (int nf = 0; nf < 4; nf++)
                    mma16816(c[mf][nf], ah[mf],
                             bh[nf >> 1][(nf & 1) * 2], bh[nf >> 1][(nf & 1) * 2 + 1]);
            #pragma unroll
            for (int mf = 0; mf < 4; mf++)
                #pragma unroll
                for (int nf = 0; nf < 4; nf++)
                    mma16816(c[mf][nf], al[mf],
                             bh[nf >> 1][(nf & 1) * 2], bh[nf >> 1][(nf & 1) * 2 + 1]);
            #pragma unroll
            for (int mf = 0; mf < 4; mf++)
                #pragma unroll
                for (int nf = 0; nf < 4; nf++)
                    mma16816(c[mf][nf], ah[mf],
                             bl[nf >> 1][(nf & 1) * 2], bl[nf >> 1][(nf & 1) * 2 + 1]);
        }
        __syncthreads();
    }

    // ---- epilogue ----
    #pragma unroll
    for (int mf = 0; mf < 4; mf++) {
        int r0 = bm + wmo + mf * 16 + (lane >> 2);
        #pragma unroll
        for (int nf = 0; nf < 4; nf++) {
            int col = bn + wno + nf * 8 + (lane & 3) * 2;
            #pragma unroll
            for (int h = 0; h < 2; h++) {
                int row = r0 + h * 8;
                if (row >= M) continue;
                float v0 = c[mf][nf][h * 2], v1 = c[mf][nf][h * 2 + 1];
                if (EPI == 1) {
                    float b0 = bias[col], b1 = bias[col + 1];
                    size_t ti = (size_t)row * NGLOB + col;
                    uint32_t ph = *(const uint32_t*)(Thi + ti);
                    uint32_t pl = *(const uint32_t*)(Tlo + ti);
                    float t0 = bfl(ph) + bfl(pl);
                    float t1 = bfh(ph) + bfh(pl);
                    float r0v = t0 * (1.f / (1.f + __expf(-(v0 + b0))));
                    float r1v = t1 * (1.f / (1.f + __expf(-(v1 + b1))));
                    bf16 h0, h1, l0, l1;
                    split1(r0v, h0, l0); split1(r1v, h1, l1);
                    *(uint32_t*)(Chi + ti) = pck(h0, h1);
                    *(uint32_t*)(Clo + ti) = pck(l0, l1);
                } else {
                    v0 += bias[col]; v1 += bias[col + 1];
                    if (g_flag[row0 + row]) { v0 = 0.f; v1 = 0.f; }
                    *(float2*)(Cf + (size_t)row * NGLOB + col) = make_float2(v0, v1);
                }
            }
        }
    }
}

// --------------------------------- launcher ----------------------------------
extern "C" void kernel_launch(void* const* d_in, const int* in_sizes, int n_in,
                              void* d_out, int out_size)
{
    const float* x_u    = (const float*)d_in[0];
    const float* x_v    = (const float*)d_in[1];
    const float* W_r1   = (const float*)d_in[2];
    const float* W_r2   = (const float*)d_in[3];
    const float* W_gate = (const float*)d_in[4];
    const float* b_gate = (const float*)d_in[5];
    const float* W_aggr = (const float*)d_in[6];
    const float* b_aggr = (const float*)d_in[7];
    const int*   ei1    = (const int*)d_in[8];
    const int*   ei2    = (const int*)d_in[9];

    const int n_u = in_sizes[0] / D_FEAT;
    const int n_v = in_sizes[1] / D_FEAT;
    const int E1  = in_sizes[8] / 2;
    const int E2  = in_sizes[9] / 2;

    const int SMEM = 65536;
    cudaFuncSetAttribute((k_mma<128, 128>),     cudaFuncAttributeMaxDynamicSharedMemorySize, SMEM);
    cudaFuncSetAttribute((k_mma2<384, 384, 1>), cudaFuncAttributeMaxDynamicSharedMemorySize, SMEM);
    cudaFuncSetAttribute((k_mma2<384, 128, 2>), cudaFuncAttributeMaxDynamicSharedMemorySize, SMEM);

    static cudaStream_t s2 = nullptr;
    static cudaEvent_t evFork = nullptr, evJoin = nullptr, evEnd = nullptr;
    static cudaEvent_t evA[3] = {nullptr, nullptr, nullptr};
    if (!s2) {
        cudaStreamCreateWithFlags(&s2, cudaStreamNonBlocking);
        cudaEventCreateWithFlags(&evFork, cudaEventDisableTiming);
        cudaEventCreateWithFlags(&evJoin, cudaEventDisableTiming);
        cudaEventCreateWithFlags(&evEnd, cudaEventDisableTiming);
        for (int i = 0; i < 3; i++)
            cudaEventCreateWithFlags(&evA[i], cudaEventDisableTiming);
    }

    void *p_hu, *p_hv, *p_cnt;
    void *p_th, *p_tl, *p_2h, *p_2l;
    void *p_w1h, *p_w1l, *p_w2h, *p_w2l, *p_wgh, *p_wgl, *p_wah, *p_wal;
    cudaGetSymbolAddress(&p_hu, g_hu);      cudaGetSymbolAddress(&p_hv, g_hv);
    cudaGetSymbolAddress(&p_cnt, g_cnt);
    cudaGetSymbolAddress(&p_th, g_tot_hi);  cudaGetSymbolAddress(&p_tl, g_tot_lo);
    cudaGetSymbolAddress(&p_2h, g_t2_hi);   cudaGetSymbolAddress(&p_2l, g_t2_lo);
    cudaGetSymbolAddress(&p_w1h, g_w1t_hi); cudaGetSymbolAddress(&p_w1l, g_w1t_lo);
    cudaGetSymbolAddress(&p_w2h, g_w2t_hi); cudaGetSymbolAddress(&p_w2l, g_w2t_lo);
    cudaGetSymbolAddress(&p_wgh, g_wgt_hi); cudaGetSymbolAddress(&p_wgl, g_wgt_lo);
    cudaGetSymbolAddress(&p_wah, g_wat_hi); cudaGetSymbolAddress(&p_wal, g_wat_lo);

    // ---- fork: CSR + gate/aggr weight splits on s2; transforms on main ----
    cudaEventRecord(evFork, 0);
    cudaStreamWaitEvent(s2, evFork, 0);

    cudaMemsetAsync(p_cnt, 0, (size_t)n_v * sizeof(int), s2);
    k_hist<<<2048, 256, 0, s2>>>(ei1, ei2, E1, E2);
    int nb = (n_v + 511) / 512;
    k_scan_a<<<nb, 256, 0, s2>>>(n_v);
    k_scan_b<<<1, 256, 0, s2>>>(nb, n_v);
    k_scan_c<<<nb, 256, 0, s2>>>(n_v);
    k_fill<<<2048, 256, 0, s2>>>(ei1, ei2, E1, E2);
    k_wsplit<<<(384 * 384 + 255) / 256, 256, 0, s2>>>(W_gate, (bf16*)p_wgh, (bf16*)p_wgl, 384, 384);
    k_wsplit<<<(384 * 128 + 255) / 256, 256, 0, s2>>>(W_aggr, (bf16*)p_wah, (bf16*)p_wal, 384, 128);
    cudaEventRecord(evJoin, s2);

    // main: merged r1/r2 weight split + node transforms
    k_wsplit2<<<(2 * 128 * 128 + 255) / 256, 256>>>(
        W_r1, (bf16*)p_w1h, (bf16*)p_w1l, W_r2, (bf16*)p_w2h, (bf16*)p_w2l);
    k_mma<128, 128><<<dim3(1, (n_u + 127) / 128), 256, SMEM>>>(
        x_u, (const bf16*)p_w1h, (const bf16*)p_w1l, (float*)p_hu, n_u);
    k_mma<128, 128><<<dim3(1, (n_v + 127) / 128), 256, SMEM>>>(
        x_v, (const bf16*)p_w2h, (const bf16*)p_w2l, (float*)p_hv, n_v);

    // ---- join, then 4-chunk aggregate/GEMM pipeline over node rows ----
    cudaStreamWaitEvent(0, evJoin, 0);

    int Hc = ((n_v / 4 + 127) / 128) * 128;
    int starts[5];
    for (int c = 0; c < 5; c++) {
        int s = c * Hc;
        starts[c] = (s > n_v) ? n_v : s;
    }
    starts[4] = n_v;

    // main: aggregate all 4 chunks in order, signaling after chunks 0-2
    for (int c = 0; c < 4; c++) {
        int a = starts[c], b = starts[c + 1];
        if (b > a)
            k_aggr<<<((b - a) * 32 + 255) / 256, 256>>>(a, b);
        if (c < 3) cudaEventRecord(evA[c], 0);
    }

    // s2: gate + aggr GEMMs for chunks 0-2, overlapped with later aggregates
    for (int c = 0; c < 3; c++) {
        int a = starts[c], b = starts[c + 1];
        if (b <= a) continue;
        int rows = b - a;
        cudaStreamWaitEvent(s2, evA[c], 0);
        const bf16* th = (const bf16*)p_th + (size_t)a * 384;
        const bf16* tl = (const bf16*)p_tl + (size_t)a * 384;
        bf16* t2h = (bf16*)p_2h + (size_t)a * 384;
        bf16* t2l = (bf16*)p_2l + (size_t)a * 384;
        k_mma2<384, 384, 1><<<dim3(3, (rows + 127) / 128), 256, SMEM, s2>>>(
            th, tl, (const bf16*)p_wgh, (const bf16*)p_wgl, b_gate,
            th, tl, t2h, t2l, nullptr, rows, a);
        k_mma2<384, 128, 2><<<dim3(1, (rows + 127) / 128), 256, SMEM, s2>>>(
            t2h, t2l, (const bf16*)p_wah, (const bf16*)p_wal, b_aggr,
            nullptr, nullptr, nullptr, nullptr,
            (float*)d_out + (size_t)a * 128, rows, a);
    }
    cudaEventRecord(evEnd, s2);

    // main: gate + aggr GEMMs for the last chunk
    {
        int a = starts[3], b = starts[4];
        if (b > a) {
            int rows = b - a;
            const bf16* th = (const bf16*)p_th + (size_t)a * 384;
            const bf16* tl = (const bf16*)p_tl + (size_t)a * 384;
            bf16* t2h = (bf16*)p_2h + (size_t)a * 384;
            bf16* t2l = (bf16*)p_2l + (size_t)a * 384;
            k_mma2<384, 384, 1><<<dim3(3, (rows + 127) / 128), 256, SMEM>>>(
                th, tl, (const bf16*)p_wgh, (const bf16*)p_wgl, b_gate,
                th, tl, t2h, t2l, nullptr, rows, a);
            k_mma2<384, 128, 2><<<dim3(1, (rows + 127) / 128), 256, SMEM>>>(
                t2h, t2l, (const bf16*)p_wah, (const bf16*)p_wal, b_aggr,
                nullptr, nullptr, nullptr, nullptr,
                (float*)d_out + (size_t)a * 128, rows, a);
        }
    }
    cudaStreamWaitEvent(0, evEnd, 0);
}

// round 13
// speedup vs baseline: 1.0574x; 1.0574x over previous
#include <cuda_runtime.h>
#include <cuda_bf16.h>
#include <cstdint>
#include <math.h>

#define D_FEAT 128
#define MAXN   100000
#define MAXE   6400000

typedef __nv_bfloat16 bf16;

// ---------------- static device scratch (no allocations allowed) -------------
__device__ float g_hu[(size_t)MAXN * 128];
__device__ float g_hv[(size_t)MAXN * 128];
__device__ bf16  g_tot_hi[(size_t)MAXN * 384];
__device__ bf16  g_tot_lo[(size_t)MAXN * 384];
__device__ bf16  g_t2_hi[(size_t)MAXN * 384];
__device__ bf16  g_t2_lo[(size_t)MAXN * 384];
__device__ bf16  g_w1t_hi[128 * 128], g_w1t_lo[128 * 128];
__device__ bf16  g_w2t_hi[128 * 128], g_w2t_lo[128 * 128];
__device__ bf16  g_wgt_hi[384 * 384], g_wgt_lo[384 * 384];
__device__ bf16  g_wat_hi[128 * 384], g_wat_lo[128 * 384];
__device__ unsigned      g_esrc[MAXE];
__device__ int           g_cnt[MAXN];
__device__ int           g_row[MAXN + 1];
__device__ int           g_cur[MAXN + 1];
__device__ int           g_part[1024];
__device__ int           g_base[1024];
__device__ unsigned char g_flag[MAXN];

// ----------------------------- helpers ----------------------------------------
__device__ __forceinline__ uint32_t smem_u32(const void* p) {
    uint32_t a;
    asm("{ .reg .u64 t; cvta.to.shared.u64 t, %1; cvt.u32.u64 %0, t; }"
        : "=r"(a) : "l"(p));
    return a;
}
__device__ __forceinline__ void split1(float v, bf16& h, bf16& l) {
    h = __float2bfloat16_rn(v);
    l = __float2bfloat16_rn(v - __bfloat162float(h));
}
__device__ __forceinline__ uint32_t pck(bf16 a, bf16 b) {
    return ((uint32_t)__bfloat16_as_ushort(b) << 16) | __bfloat16_as_ushort(a);
}
__device__ __forceinline__ void split4_store(bf16* hi, bf16* lo, size_t off, float4 v) {
    bf16 h0, h1, h2, h3, l0, l1, l2, l3;
    split1(v.x, h0, l0); split1(v.y, h1, l1);
    split1(v.z, h2, l2); split1(v.w, h3, l3);
    uint2 uh = make_uint2(pck(h0, h1), pck(h2, h3));
    uint2 ul = make_uint2(pck(l0, l1), pck(l2, l3));
    *(uint2*)(hi + off) = uh;
    *(uint2*)(lo + off) = ul;
}
__device__ __forceinline__ float bfl(uint32_t u) {
    return __bfloat162float(__ushort_as_bfloat16((unsigned short)(u & 0xffff)));
}
__device__ __forceinline__ float bfh(uint32_t u) {
    return __bfloat162float(__ushort_as_bfloat16((unsigned short)(u >> 16)));
}
__device__ __forceinline__ void ldmx4(uint32_t* r, uint32_t addr) {
    asm volatile("ldmatrix.sync.aligned.m8n8.x4.shared.b16 {%0,%1,%2,%3}, [%4];"
                 : "=r"(r[0]), "=r"(r[1]), "=r"(r[2]), "=r"(r[3]) : "r"(addr));
}
__device__ __forceinline__ void mma16816(float* c, const uint32_t* a,
                                         uint32_t b0, uint32_t b1) {
    asm volatile(
        "mma.sync.aligned.m16n8k16.row.col.f32.bf16.bf16.f32 "
        "{%0,%1,%2,%3}, {%4,%5,%6,%7}, {%8,%9}, {%0,%1,%2,%3};"
        : "+f"(c[0]), "+f"(c[1]), "+f"(c[2]), "+f"(c[3])
        : "r"(a[0]), "r"(a[1]), "r"(a[2]), "r"(a[3]), "r"(b0), "r"(b1));
}
// swizzled byte offset within a [128 rows x 128B] tile (K-chunk 64)
__device__ __forceinline__ uint32_t swz(int row, int g16) {
    return ((uint32_t)row << 7) + (((uint32_t)g16 ^ ((uint32_t)row & 7)) << 4);
}
// swizzled byte offset within a [128 rows x 64B] tile (K-chunk 32)
__device__ __forceinline__ uint32_t swz32(int row, int g16) {
    return ((uint32_t)row << 6) + (((uint32_t)g16 ^ (((uint32_t)row >> 1) & 3)) << 4);
}
#define CP16(dst, src) \
    asm volatile("cp.async.cg.shared.global [%0], [%1], 16;" :: "r"(dst), "l"(src))
#define CP_COMMIT() asm volatile("cp.async.commit_group;")

// ------------------------------- small kernels -------------------------------
// two transposed weight splits in one launch (r1 then r2)
__global__ void k_wsplit2(const float* __restrict__ W1, bf16* __restrict__ b1h,
                          bf16* __restrict__ b1l,
                          const float* __restrict__ W2, bf16* __restrict__ b2h,
                          bf16* __restrict__ b2l) {
    int i = blockIdx.x * blockDim.x + threadIdx.x;
    const int KN = 128 * 128;
    const float* W = (i < KN) ? W1 : W2;
    bf16* bh = (i < KN) ? b1h : b2h;
    bf16* bl = (i < KN) ? b1l : b2l;
    int j = (i < KN) ? i : i - KN;
    if (j >= KN) return;
    int n = j >> 7, k = j & 127;
    bf16 h, l; split1(W[(size_t)k * 128 + n], h, l);
    bh[j] = h; bl[j] = l;
}

__global__ void k_wsplit(const float* __restrict__ W, bf16* __restrict__ bhi,
                         bf16* __restrict__ blo, int K, int N) {
    int i = blockIdx.x * blockDim.x + threadIdx.x;
    if (i >= K * N) return;
    int n = i / K, k = i % K;
    bf16 h, l; split1(W[(size_t)k * N + n], h, l);
    bhi[i] = h; blo[i] = l;
}

__global__ void k_hist(const int* __restrict__ e1, const int* __restrict__ e2,
                       int E1, int E2) {
    int stride = gridDim.x * blockDim.x;
    int ET = E1 + E2;
    for (int i = blockIdx.x * blockDim.x + threadIdx.x; i < ET; i += stride) {
        int d = (i < E1) ? e1[E1 + i] : e2[E2 + (i - E1)];
        atomicAdd(&g_cnt[d], 1);
    }
}

__global__ void k_scan_a(int n) {
    int b = blockIdx.x, t = threadIdx.x;
    int i0 = b * 512 + t;
    int s = 0;
    if (i0 < n)       s += g_cnt[i0];
    if (i0 + 256 < n) s += g_cnt[i0 + 256];
    __shared__ int sm[256];
    sm[t] = s; __syncthreads();
    for (int off = 128; off > 0; off >>= 1) {
        if (t < off) sm[t] += sm[t + off];
        __syncthreads();
    }
    if (t == 0) g_part[b] = sm[0];
}

__global__ void k_scan_b(int nb, int n) {
    int t = threadIdx.x;
    __shared__ int sm[256];
    sm[t] = (t < nb) ? g_part[t] : 0;
    __syncthreads();
    for (int off = 1; off < 256; off <<= 1) {
        int x = (t >= off) ? sm[t - off] : 0;
        __syncthreads();
        sm[t] += x;
        __syncthreads();
    }
    int excl = (t == 0) ? 0 : sm[t - 1];
    if (t < nb) g_base[t] = excl;
    if (t == 255) { g_row[n] = sm[255]; g_cur[n] = sm[255]; }
}

__global__ void k_scan_c(int n) {
    int b = blockIdx.x, t = threadIdx.x;
    int i0 = b * 512 + t * 2;
    int a0 = (i0 < n)     ? g_cnt[i0]     : 0;
    int a1 = (i0 + 1 < n) ? g_cnt[i0 + 1] : 0;
    __shared__ int sm[256];
    sm[t] = a0 + a1; __syncthreads();
    for (int off = 1; off < 256; off <<= 1) {
        int x = (t >= off) ? sm[t - off] : 0;
        __syncthreads();
        sm[t] += x;
        __syncthreads();
    }
    int excl = (t == 0) ? 0 : sm[t - 1];
    int base = g_base[b] + excl;
    if (i0 < n)     { g_row[i0]     = base;      g_cur[i0]     = base; }
    if (i0 + 1 < n) { g_row[i0 + 1] = base + a0; g_cur[i0 + 1] = base + a0; }
}

__global__ void k_fill(const int* __restrict__ e1, const int* __restrict__ e2,
                       int E1, int E2) {
    int stride = gridDim.x * blockDim.x;
    int ET = E1 + E2;
    for (int i = blockIdx.x * blockDim.x + threadIdx.x; i < ET; i += stride) {
        int s, d; unsigned rel;
        if (i < E1) { s = e1[i]; d = e1[E1 + i]; rel = 0u; }
        else { int j = i - E1; s = e2[j]; d = e2[E2 + j]; rel = 0x80000000u; }
        int pos = atomicAdd(&g_cur[d], 1);
        g_esrc[pos] = (unsigned)s | rel;
    }
}

// ---------------- per-node aggregation: one warp per destination -------------
__device__ __forceinline__ void acc4(float4& s, float4& m, const float4 v) {
    s.x += v.x; s.y += v.y; s.z += v.z; s.w += v.w;
    m.x = fmaxf(m.x, v.x); m.y = fmaxf(m.y, v.y);
    m.z = fmaxf(m.z, v.z); m.w = fmaxf(m.w, v.w);
}
__device__ __forceinline__ const float4* hsel(unsigned p) {
    return (p & 0x80000000u) ? (const float4*)g_hv : (const float4*)g_hu;
}

__global__ void k_aggr(int n0, int n1) {
    int w = n0 + ((blockIdx.x * blockDim.x + threadIdx.x) >> 5);
    int lane = threadIdx.x & 31;
    if (w >= n1) return;
    int beg = g_row[w], end = g_row[w + 1];
    float4 s = make_float4(0.f, 0.f, 0.f, 0.f);
    float4 m = s;  // max clamped to 0 (reference does max(segmax, 0))
    int e = beg;
    for (; e + 3 < end; e += 4) {
        unsigned p0 = g_esrc[e],     p1 = g_esrc[e + 1];
        unsigned p2 = g_esrc[e + 2], p3 = g_esrc[e + 3];
        float4 v0 = __ldg(hsel(p0) + (size_t)(p0 & 0x7fffffffu) * 32 + lane);
        float4 v1 = __ldg(hsel(p1) + (size_t)(p1 & 0x7fffffffu) * 32 + lane);
        float4 v2 = __ldg(hsel(p2) + (size_t)(p2 & 0x7fffffffu) * 32 + lane);
        float4 v3 = __ldg(hsel(p3) + (size_t)(p3 & 0x7fffffffu) * 32 + lane);
        acc4(s, m, v0); acc4(s, m, v1); acc4(s, m, v2); acc4(s, m, v3);
    }
    for (; e < end; e++) {
        unsigned p = g_esrc[e];
        float4 v = __ldg(hsel(p) + (size_t)(p & 0x7fffffffu) * 32 + lane);
        acc4(s, m, v);
    }
    int c = end - beg;
    float inv = (c > 0) ? 1.f / (float)c : 0.f;
    float4 mean = make_float4(s.x * inv, s.y * inv, s.z * inv, s.w * inv);

    float asum = fabsf(s.x) + fabsf(s.y) + fabsf(s.z) + fabsf(s.w)
               + fabsf(mean.x) + fabsf(mean.y) + fabsf(mean.z) + fabsf(mean.w)
               + fabsf(m.x) + fabsf(m.y) + fabsf(m.z) + fabsf(m.w);
    #pragma unroll
    for (int off = 16; off > 0; off >>= 1)
        asum += __shfl_xor_sync(0xffffffffu, asum, off);

    size_t rb = (size_t)w * 384 + lane * 4;
    split4_store(g_tot_hi, g_tot_lo, rb,       s);
    split4_store(g_tot_hi, g_tot_lo, rb + 128, mean);
    split4_store(g_tot_hi, g_tot_lo, rb + 256, m);
    if (lane == 0) g_flag[w] = (asum == 0.f) ? 1 : 0;
}

// ------ transforms: bf16-split GEMM, fp32 A split in-kernel (proven R8/R9) ---
template <int K, int NGLOB>
__global__ __launch_bounds__(256, 2)
void k_mma(const float* __restrict__ A,
           const bf16* __restrict__ Bhi, const bf16* __restrict__ Blo,
           float* __restrict__ C, int M)
{
    extern __shared__ char sm_[];
    const uint32_t sbase = smem_u32(sm_);
    const int tid = threadIdx.x;
    const int bm = blockIdx.y * 128;
    const int bn = blockIdx.x * 128;
    const int wid = tid >> 5, lane = tid & 31;
    const int wmo = (wid >> 2) * 64;
    const int wno = (wid & 3) * 32;

    float c[4][4][4];
    #pragma unroll
    for (int i = 0; i < 4; i++)
        #pragma unroll
        for (int j = 0; j < 4; j++)
            #pragma unroll
            for (int r = 0; r < 4; r++) c[i][j][r] = 0.f;

    for (int kc = 0; kc < K / 64; kc++) {
        #pragma unroll
        for (int it = 0; it < 4; it++) {
            int tsk = tid + it * 256;
            int r = tsk >> 3, g = tsk & 7;
            int gr = bm + r;
            float4 f0 = make_float4(0.f, 0.f, 0.f, 0.f), f1 = f0;
            if (gr < M) {
                const float4* p = (const float4*)(A + (size_t)gr * K + kc * 64 + g * 8);
                f0 = p[0]; f1 = p[1];
            }
            bf16 h[8], l[8];
            split1(f0.x, h[0], l[0]); split1(f0.y, h[1], l[1]);
            split1(f0.z, h[2], l[2]); split1(f0.w, h[3], l[3]);
            split1(f1.x, h[4], l[4]); split1(f1.y, h[5], l[5]);
            split1(f1.z, h[6], l[6]); split1(f1.w, h[7], l[7]);
            uint4 uh = make_uint4(pck(h[0], h[1]), pck(h[2], h[3]),
                                  pck(h[4], h[5]), pck(h[6], h[7]));
            uint4 ul = make_uint4(pck(l[0], l[1]), pck(l[2], l[3]),
                                  pck(l[4], l[5]), pck(l[6], l[7]));
            uint32_t off = swz(r, g);
            *(uint4*)(sm_ + off)         = uh;
            *(uint4*)(sm_ + 16384 + off) = ul;
        }
        #pragma unroll
        for (int it = 0; it < 4; it++) {
            int tsk = tid + it * 256;
            int r = tsk >> 3, g = tsk & 7;
            uint32_t off = swz(r, g);
            *(uint4*)(sm_ + 32768 + off) =
                *(const uint4*)(Bhi + (size_t)(bn + r) * K + kc * 64 + g * 8);
            *(uint4*)(sm_ + 49152 + off) =
                *(const uint4*)(Blo + (size_t)(bn + r) * K + kc * 64 + g * 8);
        }
        __syncthreads();

        #pragma unroll
        for (int ks = 0; ks < 4; ks++) {
            uint32_t ah[4][4], al[4][4], bh[2][4], bl[2][4];
            #pragma unroll
            for (int mf = 0; mf < 4; mf++) {
                int row = wmo + mf * 16 + (lane & 15);
                int g = ks * 2 + (lane >> 4);
                uint32_t o = swz(row, g);
                ldmx4(ah[mf], sbase + o);
                ldmx4(al[mf], sbase + 16384 + o);
            }
            #pragma unroll
            for (int np = 0; np < 2; np++) {
                int row = wno + np * 16 + ((lane >> 4) << 3) + (lane & 7);
                int g = ks * 2 + ((lane >> 3) & 1);
                uint32_t o = swz(row, g);
                ldmx4(bh[np], sbase + 32768 + o);
                ldmx4(bl[np], sbase + 49152 + o);
            }
            #pragma unroll
            for (int mf = 0; mf < 4; mf++)
                #pragma unroll
                for (int nf = 0; nf < 4; nf++)
                    mma16816(c[mf][nf], ah[mf],
                             bh[nf >> 1][(nf & 1) * 2], bh[nf >> 1][(nf & 1) * 2 + 1]);
            #pragma unroll
            for (int mf = 0; mf < 4; mf++)
                #pragma unroll
                for (int nf = 0; nf < 4; nf++)
                    mma16816(c[mf][nf], al[mf],
                             bh[nf >> 1][(nf & 1) * 2], bh[nf >> 1][(nf & 1) * 2 + 1]);
            #pragma unroll
            for (int mf = 0; mf < 4; mf++)
                #pragma unroll
                for (int nf = 0; nf < 4; nf++)
                    mma16816(c[mf][nf], ah[mf],
                             bl[nf >> 1][(nf & 1) * 2], bl[nf >> 1][(nf & 1) * 2 + 1]);
        }
        __syncthreads();
    }

    #pragma unroll
    for (int mf = 0; mf < 4; mf++) {
        int r0 = bm + wmo + mf * 16 + (lane >> 2);
        #pragma unroll
        for (int nf = 0; nf < 4; nf++) {
            int col = bn + wno + nf * 8 + (lane & 3) * 2;
            #pragma unroll
            for (int h = 0; h < 2; h++) {
                int row = r0 + h * 8;
                if (row >= M) continue;
                *(float2*)(C + (size_t)row * NGLOB + col) =
                    make_float2(c[mf][nf][h * 2], c[mf][nf][h * 2 + 1]);
            }
        }
    }
}

// ------ gate/aggr GEMMs: all-bf16 operands, cp.async 2-stage double buffer ---
// C = A[M,K] @ B[NGLOB,K]^T, 3-term: Ah*Bh + Al*Bh + Ah*Bl
// (2-term measured FAIL at 1.4e-3 in R7 — do not retry.)
// row0 = global row offset of this chunk (for g_flag indexing).
// EPI 1: t = Thi+Tlo; r = t * sigmoid(result + bias); write split(r) -> Chi/Clo
// EPI 2: Cf = result + bias, zeroed where g_flag[row0+row]
template <int K, int NGLOB, int EPI>
__global__ __launch_bounds__(256, 2)
void k_mma2(const bf16* __restrict__ Ahi, const bf16* __restrict__ Alo,
            const bf16* __restrict__ Bhi, const bf16* __restrict__ Blo,
            const float* __restrict__ bias,
            const bf16* __restrict__ Thi, const bf16* __restrict__ Tlo,
            bf16* __restrict__ Chi, bf16* __restrict__ Clo,
            float* __restrict__ Cf, int M, int row0)
{
    constexpr int NKC = K / 32;
    extern __shared__ char sm_[];
    // per stage (32 KB): Ah[0,8K) Al[8K,16K) Bh[16K,24K) Bl[24K,32K)
    const uint32_t sbase = smem_u32(sm_);
    const int tid = threadIdx.x;
    const int bm = blockIdx.y * 128;
    const int bn = blockIdx.x * 128;
    const int wid = tid >> 5, lane = tid & 31;
    const int wmo = (wid >> 2) * 64;
    const int wno = (wid & 3) * 32;

    float c[4][4][4];
    #pragma unroll
    for (int i = 0; i < 4; i++)
        #pragma unroll
        for (int j = 0; j < 4; j++)
            #pragma unroll
            for (int r = 0; r < 4; r++) c[i][j][r] = 0.f;

    int r0s = tid >> 2, g0s = tid & 3;
    int r1s = (tid + 256) >> 2, g1s = tid & 3;
    int ga0 = bm + r0s; if (ga0 >= M) ga0 = M - 1;
    int ga1 = bm + r1s; if (ga1 >= M) ga1 = M - 1;
    uint32_t o0 = swz32(r0s, g0s), o1 = swz32(r1s, g1s);

    auto stage = [&](int kc, int buf) {
        uint32_t sb = sbase + buf * 32768;
        const bf16* pa;
        pa = Ahi + (size_t)ga0 * K + kc * 32 + g0s * 8; CP16(sb + o0, pa);
        pa = Ahi + (size_t)ga1 * K + kc * 32 + g1s * 8; CP16(sb + o1, pa);
        pa = Alo + (size_t)ga0 * K + kc * 32 + g0s * 8; CP16(sb + 8192 + o0, pa);
        pa = Alo + (size_t)ga1 * K + kc * 32 + g1s * 8; CP16(sb + 8192 + o1, pa);
        pa = Bhi + (size_t)(bn + r0s) * K + kc * 32 + g0s * 8; CP16(sb + 16384 + o0, pa);
        pa = Bhi + (size_t)(bn + r1s) * K + kc * 32 + g1s * 8; CP16(sb + 16384 + o1, pa);
        pa = Blo + (size_t)(bn + r0s) * K + kc * 32 + g0s * 8; CP16(sb + 24576 + o0, pa);
        pa = Blo + (size_t)(bn + r1s) * K + kc * 32 + g1s * 8; CP16(sb + 24576 + o1, pa);
        CP_COMMIT();
    };

    stage(0, 0);
    for (int kc = 0; kc < NKC; kc++) {
        if (kc + 1 < NKC) {
            stage(kc + 1, (kc + 1) & 1);
            asm volatile("cp.async.wait_group 1;");
        } else {
            asm volatile("cp.async.wait_group 0;");
        }
        __syncthreads();
        const uint32_t sb = sbase + (kc & 1) * 32768;

        #pragma unroll
        for (int ks = 0; ks < 2; ks++) {
            uint32_t ah[4][4], al[4][4], bh[2][4], bl[2][4];
            #pragma unroll
            for (int mf = 0; mf < 4; mf++) {
                int row = wmo + mf * 16 + (lane & 15);
                int g = ks * 2 + (lane >> 4);
                uint32_t o = swz32(row, g);
                ldmx4(ah[mf], sb + o);
                ldmx4(al[mf], sb + 8192 + o);
            }
            #pragma unroll
            for (int np = 0; np < 2; np++) {
                int row = wno + np * 16 + ((lane >> 4) << 3) + (lane & 7);
                int g = ks * 2 + ((lane >> 3) & 1);
                uint32_t o = swz32(row, g);
                ldmx4(bh[np], sb + 16384 + o);
                ldmx4(bl[np], sb + 24576 + o);
            }
            #pragma unroll
            for (int mf = 0; mf < 4; mf++)
                #pragma unroll
                for (int nf = 0; nf < 4; nf++)
                    mma16816(c[mf][nf], ah[mf],
                             bh[nf >> 1][(nf & 1) * 2], bh[nf >> 1][(nf & 1) * 2 + 1]);
            #pragma unroll
            for (int mf = 0; mf < 4; mf++)
                #pragma unroll
                for (int nf = 0; nf < 4; nf++)
                    mma16816(c[mf][nf], al[mf],
                             bh[nf >> 1][(nf & 1) * 2], bh[nf >> 1][(nf & 1) * 2 + 1]);
            #pragma unroll
            for (int mf = 0; mf < 4; mf++)
                #pragma unroll
                for (int nf = 0; nf < 4; nf++)
                    mma16816(c[mf][nf], ah[mf],
                             bl[nf >> 1][(nf & 1) * 2], bl[nf >> 1][(nf & 1) * 2 + 1]);
        }
        __syncthreads();
    }

    // ---- epilogue ----
    #pragma unroll
    for (int mf = 0; mf < 4; mf++) {
        int r0 = bm + wmo + mf * 16 + (lane >> 2);
        #pragma unroll
        for (int nf = 0; nf < 4; nf++) {
            int col = bn + wno + nf * 8 + (lane & 3) * 2;
            #pragma unroll
            for (int h = 0; h < 2; h++) {
                int row = r0 + h * 8;
                if (row >= M) continue;
                float v0 = c[mf][nf][h * 2], v1 = c[mf][nf][h * 2 + 1];
                if (EPI == 1) {
                    float b0 = bias[col], b1 = bias[col + 1];
                    size_t ti = (size_t)row * NGLOB + col;
                    uint32_t ph = *(const uint32_t*)(Thi + ti);
                    uint32_t pl = *(const uint32_t*)(Tlo + ti);
                    float t0 = bfl(ph) + bfl(pl);
                    float t1 = bfh(ph) + bfh(pl);
                    float r0v = t0 * (1.f / (1.f + __expf(-(v0 + b0))));
                    float r1v = t1 * (1.f / (1.f + __expf(-(v1 + b1))));
                    bf16 h0, h1, l0, l1;
                    split1(r0v, h0, l0); split1(r1v, h1, l1);
                    *(uint32_t*)(Chi + ti) = pck(h0, h1);
                    *(uint32_t*)(Clo + ti) = pck(l0, l1);
                } else {
                    v0 += bias[col]; v1 += bias[col + 1];
                    if (g_flag[row0 + row]) { v0 = 0.f; v1 = 0.f; }
                    *(float2*)(Cf + (size_t)row * NGLOB + col) = make_float2(v0, v1);
                }
            }
        }
    }
}

// --------------------------------- launcher ----------------------------------
extern "C" void kernel_launch(void* const* d_in, const int* in_sizes, int n_in,
                              void* d_out, int out_size)
{
    const float* x_u    = (const float*)d_in[0];
    const float* x_v    = (const float*)d_in[1];
    const float* W_r1   = (const float*)d_in[2];
    const float* W_r2   = (const float*)d_in[3];
    const float* W_gate = (const float*)d_in[4];
    const float* b_gate = (const float*)d_in[5];
    const float* W_aggr = (const float*)d_in[6];
    const float* b_aggr = (const float*)d_in[7];
    const int*   ei1    = (const int*)d_in[8];
    const int*   ei2    = (const int*)d_in[9];

    const int n_u = in_sizes[0] / D_FEAT;
    const int n_v = in_sizes[1] / D_FEAT;
    const int E1  = in_sizes[8] / 2;
    const int E2  = in_sizes[9] / 2;

    const int SMEM = 65536;
    cudaFuncSetAttribute((k_mma<128, 128>),     cudaFuncAttributeMaxDynamicSharedMemorySize, SMEM);
    cudaFuncSetAttribute((k_mma2<384, 384, 1>), cudaFuncAttributeMaxDynamicSharedMemorySize, SMEM);
    cudaFuncSetAttribute((k_mma2<384, 128, 2>), cudaFuncAttributeMaxDynamicSharedMemorySize, SMEM);

    static cudaStream_t s2 = nullptr;
    static cudaEvent_t evFork = nullptr, evJoin = nullptr, evA0 = nullptr, evEnd = nullptr;
    if (!s2) {
        cudaStreamCreateWithFlags(&s2, cudaStreamNonBlocking);
        cudaEventCreateWithFlags(&evFork, cudaEventDisableTiming);
        cudaEventCreateWithFlags(&evJoin, cudaEventDisableTiming);
        cudaEventCreateWithFlags(&evA0, cudaEventDisableTiming);
        cudaEventCreateWithFlags(&evEnd, cudaEventDisableTiming);
    }

    void *p_hu, *p_hv, *p_cnt;
    void *p_th, *p_tl, *p_2h, *p_2l;
    void *p_w1h, *p_w1l, *p_w2h, *p_w2l, *p_wgh, *p_wgl, *p_wah, *p_wal;
    cudaGetSymbolAddress(&p_hu, g_hu);      cudaGetSymbolAddress(&p_hv, g_hv);
    cudaGetSymbolAddress(&p_cnt, g_cnt);
    cudaGetSymbolAddress(&p_th, g_tot_hi);  cudaGetSymbolAddress(&p_tl, g_tot_lo);
    cudaGetSymbolAddress(&p_2h, g_t2_hi);   cudaGetSymbolAddress(&p_2l, g_t2_lo);
    cudaGetSymbolAddress(&p_w1h, g_w1t_hi); cudaGetSymbolAddress(&p_w1l, g_w1t_lo);
    cudaGetSymbolAddress(&p_w2h, g_w2t_hi); cudaGetSymbolAddress(&p_w2l, g_w2t_lo);
    cudaGetSymbolAddress(&p_wgh, g_wgt_hi); cudaGetSymbolAddress(&p_wgl, g_wgt_lo);
    cudaGetSymbolAddress(&p_wah, g_wat_hi); cudaGetSymbolAddress(&p_wal, g_wat_lo);

    // ---- fork: CSR + gate/aggr weight splits on s2; transforms on main ----
    cudaEventRecord(evFork, 0);
    cudaStreamWaitEvent(s2, evFork, 0);

    cudaMemsetAsync(p_cnt, 0, (size_t)n_v * sizeof(int), s2);
    k_hist<<<2048, 256, 0, s2>>>(ei1, ei2, E1, E2);
    int nb = (n_v + 511) / 512;
    k_scan_a<<<nb, 256, 0, s2>>>(n_v);
    k_scan_b<<<1, 256, 0, s2>>>(nb, n_v);
    k_scan_c<<<nb, 256, 0, s2>>>(n_v);
    k_fill<<<2048, 256, 0, s2>>>(ei1, ei2, E1, E2);
    k_wsplit<<<(384 * 384 + 255) / 256, 256, 0, s2>>>(W_gate, (bf16*)p_wgh, (bf16*)p_wgl, 384, 384);
    k_wsplit<<<(384 * 128 + 255) / 256, 256, 0, s2>>>(W_aggr, (bf16*)p_wah, (bf16*)p_wal, 384, 128);
    cudaEventRecord(evJoin, s2);

    // main: merged r1/r2 weight split + node transforms
    k_wsplit2<<<(2 * 128 * 128 + 255) / 256, 256>>>(
        W_r1, (bf16*)p_w1h, (bf16*)p_w1l, W_r2, (bf16*)p_w2h, (bf16*)p_w2l);
    k_mma<128, 128><<<dim3(1, (n_u + 127) / 128), 256, SMEM>>>(
        x_u, (const bf16*)p_w1h, (const bf16*)p_w1l, (float*)p_hu, n_u);
    k_mma<128, 128><<<dim3(1, (n_v + 127) / 128), 256, SMEM>>>(
        x_v, (const bf16*)p_w2h, (const bf16*)p_w2l, (float*)p_hv, n_v);

    // ---- join, then 2-chunk aggregate/GEMM pipeline (70/30 split) ----
    cudaStreamWaitEvent(0, evJoin, 0);

    int H = (int)(((long long)n_v * 7 / 10 + 127) / 128) * 128;
    if (H > n_v) H = n_v;
    const int n1 = n_v - H;

    // main: aggregate chunk 0 (70%), signal, aggregate chunk 1 (30%)
    k_aggr<<<(H * 32 + 255) / 256, 256>>>(0, H);
    cudaEventRecord(evA0, 0);
    if (n1 > 0)
        k_aggr<<<(n1 * 32 + 255) / 256, 256>>>(H, n_v);

    // s2: gate + aggr GEMMs for chunk 0 (overlap with aggr chunk 1)
    cudaStreamWaitEvent(s2, evA0, 0);
    k_mma2<384, 384, 1><<<dim3(3, H / 128), 256, SMEM, s2>>>(
        (const bf16*)p_th, (const bf16*)p_tl,
        (const bf16*)p_wgh, (const bf16*)p_wgl, b_gate,
        (const bf16*)p_th, (const bf16*)p_tl,
        (bf16*)p_2h, (bf16*)p_2l, nullptr, H, 0);
    k_mma2<384, 128, 2><<<dim3(1, H / 128), 256, SMEM, s2>>>(
        (const bf16*)p_2h, (const bf16*)p_2l,
        (const bf16*)p_wah, (const bf16*)p_wal, b_aggr,
        nullptr, nullptr, nullptr, nullptr, (float*)d_out, H, 0);
    cudaEventRecord(evEnd, s2);

    // main: gate + aggr GEMMs for chunk 1
    if (n1 > 0) {
        const bf16* th1 = (const bf16*)p_th + (size_t)H * 384;
        const bf16* tl1 = (const bf16*)p_tl + (size_t)H * 384;
        bf16* t2h1 = (bf16*)p_2h + (size_t)H * 384;
        bf16* t2l1 = (bf16*)p_2l + (size_t)H * 384;
        k_mma2<384, 384, 1><<<dim3(3, (n1 + 127) / 128), 256, SMEM>>>(
            th1, tl1, (const bf16*)p_wgh, (const bf16*)p_wgl, b_gate,
            th1, tl1, t2h1, t2l1, nullptr, n1, H);
        k_mma2<384, 128, 2><<<dim3(1, (n1 + 127) / 128), 256, SMEM>>>(
            t2h1, t2l1, (const bf16*)p_wah, (const bf16*)p_wal, b_aggr,
            nullptr, nullptr, nullptr, nullptr,
            (float*)d_out + (size_t)H * 128, n1, H);
    }
    cudaStreamWaitEvent(0, evEnd, 0);
}